// round 13
// baseline (speedup 1.0000x reference)
#include <cuda_runtime.h>

#define B 8
#define N 2048
#define BN (B * N)
#define DELTA 1e-7f

#define TPB 1024
#define NWARP (TPB / 32)                // 32
#define CROWS 8                         // rows per chunk: 8*2048*4B = 64KB
#define NCHUNKS (N / CROWS)             // 256 chunks per batch
#define CTAS_PER_B 19
#define GRID (B * CTAS_PER_B)           // 152 CTAs = 1 per SM
#define MAXCH ((NCHUNKS + CTAS_PER_B - 1) / CTAS_PER_B)   // 14

typedef unsigned long long u64;

// Persistent scratch (__device__ globals per allocation rules).
__device__ float  g_odout1[BN];
__device__ float  g_odout2[BN];
__device__ float  g_pop1[BN];
__device__ float4 g_sir6[BN * 2];   // SIR after iter 0 (6 floats in 2x float4)
__device__ float  g_colA[BN * 4];   // iter0 colsums [OD_in, SIR_in*3] (zeroed by pass2)
__device__ float  g_colB[BN * 8];   // iter1 colsums [OD_in, SIR_in*6, pad] (zeroed by final)

__device__ __forceinline__ float dnn(float n, float d) { return (d == 0.0f) ? 0.0f : n / d; }

// ---- packed fp32x2 helpers (sm_103a dual-FMA; PTX-only) ----
__device__ __forceinline__ u64 pack2(float lo, float hi) {
    u64 r; asm("mov.b64 %0, {%1, %2};" : "=l"(r) : "f"(lo), "f"(hi)); return r;
}
__device__ __forceinline__ void unpack2(u64 v, float& lo, float& hi) {
    asm("mov.b64 {%0, %1}, %2;" : "=f"(lo), "=f"(hi) : "l"(v));
}
__device__ __forceinline__ void fma2(u64& d, u64 a, u64 b) {
    asm("fma.rn.f32x2 %0, %1, %2, %0;" : "+l"(d) : "l"(a), "l"(b));
}

// ---------------------------------------------------------------------------
// Pass 1 (iteration 0, K=4). 1024 threads, 2 cols/thread, 64KB reg chunks.
// ---------------------------------------------------------------------------
__global__ void __launch_bounds__(TPB, 1) pass1_kernel(
    const float* __restrict__ inp, const float* __restrict__ od_all)
{
    __shared__ float  s_sum[CROWS * NWARP];  // per-warp row partials
    __shared__ u64    s_wp[CROWS * 4];       // packed (w,w) weights per row
    __shared__ float4 s_st[MAXCH * CROWS];   // prefetched input features

    const int b    = blockIdx.x / CTAS_PER_B;
    const int slot = blockIdx.x % CTAS_PER_B;
    const int tid  = threadIdx.x;
    const int warp = tid >> 5, lane = tid & 31;
    const float2* ODb = reinterpret_cast<const float2*>(od_all + (size_t)(b * 2) * N * N);
    const int nch = (NCHUNKS - 1 - slot) / CTAS_PER_B + 1;   // 13 or 14

    for (int L = tid; L < nch * CROWS; L += TPB) {
        int i = (slot + (L >> 3) * CTAS_PER_B) * CROWS + (L & 7);
        s_st[L] = reinterpret_cast<const float4*>(inp)[b * N + i];
    }
    __syncthreads();

    float2 dA[CROWS], dB[CROWS];
    {   // prologue: chunk 0 -> dA
        const float2* p = ODb + (size_t)slot * CROWS * (N / 2) + tid;
#pragma unroll
        for (int r = 0; r < CROWS; r++) dA[r] = p[r * (N / 2)];
    }

    u64 acc[4] = {};   // per k; (lo,hi) = cols (2t, 2t+1)

    auto body = [&](float2 (&cur)[CROWS], float2 (&nxt)[CROWS], int c) {
        if (c + 1 < nch) {   // prefetch chunk c+1 into the other register set
            const float2* p = ODb + (size_t)(slot + (c + 1) * CTAS_PER_B) * CROWS * (N / 2) + tid;
#pragma unroll
            for (int r = 0; r < CROWS; r++) nxt[r] = p[r * (N / 2)];
        }
        // warp-level row partials via shfl
#pragma unroll
        for (int r = 0; r < CROWS; r++) {
            float s = cur[r].x + cur[r].y;
#pragma unroll
            for (int o = 16; o; o >>= 1) s += __shfl_xor_sync(0xffffffffu, s, o);
            if (lane == 0) s_sum[r * NWARP + warp] = s;
        }
        __syncthreads();   // bar1: partials visible

        if (warp < CROWS) {   // warps 0..7 reduce 32 partials for their row
            float s = s_sum[warp * NWARP + lane];
#pragma unroll
            for (int o = 16; o; o >>= 1) s += __shfl_xor_sync(0xffffffffu, s, o);
            if (lane == 0) {
                float4 f = s_st[c * CROWS + warp];
                int gi = b * N + (slot + c * CTAS_PER_B) * CROWS + warp;
                float ratio = f.x / (DELTA + s);
                float sc = ratio < 1.0f ? ratio : 1.0f;
                g_odout1[gi] = sc * s;
                float inv = 1.0f / (DELTA + f.x);
                float w1 = sc * (f.y * inv), w2 = sc * (f.z * inv), w3 = sc * (f.w * inv);
                s_wp[warp * 4 + 0] = pack2(sc, sc);
                s_wp[warp * 4 + 1] = pack2(w1, w1);
                s_wp[warp * 4 + 2] = pack2(w2, w2);
                s_wp[warp * 4 + 3] = pack2(w3, w3);
            }
        }
        __syncthreads();   // bar2: packed weights visible

        // packed K=4 accumulation: 4 FFMA2 per row
#pragma unroll
        for (int r = 0; r < CROWS; r++) {
            u64 v = pack2(cur[r].x, cur[r].y);
            const ulonglong2* wp = reinterpret_cast<const ulonglong2*>(s_wp + r * 4);
            ulonglong2 wa = wp[0], wb = wp[1];
            fma2(acc[0], v, wa.x);
            fma2(acc[1], v, wa.y);
            fma2(acc[2], v, wb.x);
            fma2(acc[3], v, wb.y);
        }
    };

    for (int c = 0; c < nch; c += 2) {
        body(dA, dB, c);
        if (c + 1 < nch) body(dB, dA, c + 1);
    }

    // flush: cols 2t (lo) and 2t+1 (hi)
#pragma unroll
    for (int k = 0; k < 4; k++) {
        float lo, hi;
        unpack2(acc[k], lo, hi);
        atomicAdd(g_colA + ((size_t)b * N + tid * 2 + 0) * 4 + k, lo);
        atomicAdd(g_colA + ((size_t)b * N + tid * 2 + 1) * 4 + k, hi);
    }
}

// ---------------------------------------------------------------------------
// Pass 2 (iteration 1, K=7). Fuses update<3> in the state prefetch.
// ---------------------------------------------------------------------------
__global__ void __launch_bounds__(TPB, 1) pass2_kernel(
    const float* __restrict__ inp, const float* __restrict__ od_all)
{
    __shared__ float  s_sum[CROWS * NWARP];
    __shared__ u64    s_wp[CROWS * 8];       // 7 packed weights per row (+pad)
    __shared__ float4 s_st[MAXCH * CROWS * 2];

    const int b    = blockIdx.x / CTAS_PER_B;
    const int slot = blockIdx.x % CTAS_PER_B;
    const int tid  = threadIdx.x;
    const int warp = tid >> 5, lane = tid & 31;
    const float2* ODb = reinterpret_cast<const float2*>(od_all + (size_t)(b * 2 + 1) * N * N);
    const int nch = (NCHUNKS - 1 - slot) / CTAS_PER_B + 1;

    // One-time prefetch + fused iter-0 state update; re-zero colA for replay
    for (int L = tid; L < nch * CROWS; L += TPB) {
        int i  = (slot + (L >> 3) * CTAS_PER_B) * CROWS + (L & 7);
        int gi = b * N + i;
        float4 f   = reinterpret_cast<const float4*>(inp)[gi];
        float4 csA = reinterpret_cast<float4*>(g_colA)[gi];
        reinterpret_cast<float4*>(g_colA)[gi] = make_float4(0, 0, 0, 0);
        float od1 = g_odout1[gi];
        float inv0 = 1.0f / (DELTA + f.x);
        float s60 = f.y - od1 * (f.y * inv0);
        float s61 = f.z - od1 * (f.z * inv0);
        float s62 = f.w - od1 * (f.w * inv0);
        float pop1 = f.x - od1 + csA.x;
        s_st[L * 2 + 0] = make_float4(pop1, s60, s61, s62);
        s_st[L * 2 + 1] = make_float4(csA.y, csA.z, csA.w, 0.0f);
        g_pop1[gi] = pop1;
        g_sir6[gi * 2 + 0] = make_float4(s60, s61, s62, csA.y);
        g_sir6[gi * 2 + 1] = make_float4(csA.z, csA.w, 0.0f, 0.0f);
    }
    __syncthreads();

    float2 dA[CROWS], dB[CROWS];
    {
        const float2* p = ODb + (size_t)slot * CROWS * (N / 2) + tid;
#pragma unroll
        for (int r = 0; r < CROWS; r++) dA[r] = p[r * (N / 2)];
    }

    u64 acc[7] = {};

    auto body = [&](float2 (&cur)[CROWS], float2 (&nxt)[CROWS], int c) {
        if (c + 1 < nch) {
            const float2* p = ODb + (size_t)(slot + (c + 1) * CTAS_PER_B) * CROWS * (N / 2) + tid;
#pragma unroll
            for (int r = 0; r < CROWS; r++) nxt[r] = p[r * (N / 2)];
        }
#pragma unroll
        for (int r = 0; r < CROWS; r++) {
            float s = cur[r].x + cur[r].y;
#pragma unroll
            for (int o = 16; o; o >>= 1) s += __shfl_xor_sync(0xffffffffu, s, o);
            if (lane == 0) s_sum[r * NWARP + warp] = s;
        }
        __syncthreads();   // bar1

        if (warp < CROWS) {
            float s = s_sum[warp * NWARP + lane];
#pragma unroll
            for (int o = 16; o; o >>= 1) s += __shfl_xor_sync(0xffffffffu, s, o);
            if (lane == 0) {
                float4 a  = s_st[(c * CROWS + warp) * 2 + 0];   // pop1, s6[0..2]
                float4 bb = s_st[(c * CROWS + warp) * 2 + 1];   // s6[3..5]
                int gi = b * N + (slot + c * CTAS_PER_B) * CROWS + warp;
                float ratio = a.x / (DELTA + s);
                float sc = ratio < 1.0f ? ratio : 1.0f;
                g_odout2[gi] = sc * s;
                float inv = 1.0f / (DELTA + a.x);
                float w[7] = {sc, sc * (a.y * inv), sc * (a.z * inv), sc * (a.w * inv),
                              sc * (bb.x * inv), sc * (bb.y * inv), sc * (bb.z * inv)};
#pragma unroll
                for (int k = 0; k < 7; k++) s_wp[warp * 8 + k] = pack2(w[k], w[k]);
                s_wp[warp * 8 + 7] = 0;
            }
        }
        __syncthreads();   // bar2

#pragma unroll
        for (int r = 0; r < CROWS; r++) {
            u64 v = pack2(cur[r].x, cur[r].y);
            const ulonglong2* wp = reinterpret_cast<const ulonglong2*>(s_wp + r * 8);
            ulonglong2 wa = wp[0], wb = wp[1], wc = wp[2], wd = wp[3];
            fma2(acc[0], v, wa.x);
            fma2(acc[1], v, wa.y);
            fma2(acc[2], v, wb.x);
            fma2(acc[3], v, wb.y);
            fma2(acc[4], v, wc.x);
            fma2(acc[5], v, wc.y);
            fma2(acc[6], v, wd.x);
            (void)wd.y;
        }
    };

    for (int c = 0; c < nch; c += 2) {
        body(dA, dB, c);
        if (c + 1 < nch) body(dB, dA, c + 1);
    }

#pragma unroll
    for (int k = 0; k < 7; k++) {
        float lo, hi;
        unpack2(acc[k], lo, hi);
        atomicAdd(g_colB + ((size_t)b * N + tid * 2 + 0) * 8 + k, lo);
        atomicAdd(g_colB + ((size_t)b * N + tid * 2 + 1) * 8 + k, hi);
    }
}

// ---------------------------------------------------------------------------
// Final: fuses update<6> + GEMM(12->64) + relu + concat(pop). Re-zeros colB.
// ---------------------------------------------------------------------------
__global__ void __launch_bounds__(256) final_kernel(
    const float* __restrict__ kern,
    const float* __restrict__ bias,
    float* __restrict__ out)
{
    __shared__ float s_kern[12 * 64];
    const int tid = threadIdx.x;
    for (int t = tid; t < 12 * 64; t += 256) s_kern[t] = kern[t];
    __syncthreads();

    const int rowl = tid >> 6;
    const int c    = tid & 63;
    const int gi   = blockIdx.x * 4 + rowl;

    float pop1   = g_pop1[gi];
    float odout2 = g_odout2[gi];
    float4 a   = g_sir6[gi * 2 + 0];
    float4 b4  = g_sir6[gi * 2 + 1];
    float4 cb0 = reinterpret_cast<const float4*>(g_colB)[gi * 2 + 0];
    float4 cb1 = reinterpret_cast<const float4*>(g_colB)[gi * 2 + 1];

    float dp1 = DELTA + pop1;
    float s12[12];
    s12[0] = a.x  - odout2 * dnn(a.x,  dp1);
    s12[1] = a.y  - odout2 * dnn(a.y,  dp1);
    s12[2] = a.z  - odout2 * dnn(a.z,  dp1);
    s12[3] = a.w  - odout2 * dnn(a.w,  dp1);
    s12[4] = b4.x - odout2 * dnn(b4.x, dp1);
    s12[5] = b4.y - odout2 * dnn(b4.y, dp1);
    s12[6]  = cb0.y; s12[7]  = cb0.z; s12[8]  = cb0.w;
    s12[9]  = cb1.x; s12[10] = cb1.y; s12[11] = cb1.z;

    float acc = __ldg(&bias[c]);
#pragma unroll
    for (int f = 0; f < 12; f++)
        acc = fmaf(s12[f], s_kern[f * 64 + c], acc);
    acc = fmaxf(acc, 0.0f);

    float* orow = out + (size_t)gi * 65;
    orow[1 + c] = acc;
    if (c == 0) orow[0] = pop1 - odout2 + cb0.x;

    __syncthreads();                  // all colB reads done before re-zero
    if (c < 8) g_colB[gi * 8 + c] = 0.0f;
}

// ---------------------------------------------------------------------------
extern "C" void kernel_launch(void* const* d_in, const int* in_sizes, int n_in,
                              void* d_out, int out_size) {
    const float* inp  = (const float*)d_in[0];  // input_feature (8,2048,4)
    const float* od   = (const float*)d_in[1];  // OD_all (8,2,2048,2048)
    const float* kern = (const float*)d_in[2];  // kernel (12,64)
    const float* bias = (const float*)d_in[3];  // bias (64)
    float* out = (float*)d_out;                 // (8,2048,65)

    pass1_kernel<<<GRID, TPB>>>(inp, od);
    pass2_kernel<<<GRID, TPB>>>(inp, od);
    final_kernel<<<BN / 4, 256>>>(kern, bias, out);
}

// round 15
// speedup vs baseline: 1.0877x; 1.0877x over previous
#include <cuda_runtime.h>

#define B 8
#define N 2048
#define BN (B * N)
#define DELTA 1e-7f

#define TPB 512
#define CROWS 8                         // rows per chunk: 8*2048*4B = 64KB
#define NCHUNKS (N / CROWS)             // 256 chunks per batch
#define CTAS_PER_B 18
#define GRID (B * CTAS_PER_B)           // 144 CTAs, 1/SM, all co-resident
#define MAXCH ((NCHUNKS + CTAS_PER_B - 1) / CTAS_PER_B)   // 15

// Persistent scratch (__device__ globals per allocation rules).
// NOTE: arrays accessed through float4 casts MUST be explicitly 16B-aligned —
// float[] only guarantees 4B and linker placement is arbitrary (R14 fault).
__device__ float    g_odout1[BN];
__device__ float    g_odout2[BN];
__device__ float    g_pop1[BN];
__device__ float4   g_sir6[BN * 2];                  // SIR after iter 0
__device__ __align__(16) float g_colA[BN * 4];       // iter0 colsums (re-zeroed in pass2)
__device__ __align__(16) float g_colB[BN * 8];       // iter1 colsums (re-zeroed in final)
__device__ unsigned g_cnt1[B];                       // monotonic per-batch phase counters
__device__ unsigned g_cnt2[B];                       // (never reset; replay-safe targets)

__device__ __forceinline__ float dnn(float n, float d) { return (d == 0.0f) ? 0.0f : n / d; }

// Per-batch phase barrier: monotonic counter, target = next multiple of 18.
// Safe across CUDA-graph replays: launches serialize, so counter values within
// one launch span exactly [18R, 18R+17].
__device__ __forceinline__ void batch_barrier(unsigned* cnt, int tid) {
    __threadfence();                      // release: all my writes visible
    __shared__ unsigned s_tgt;
    if (tid == 0) {
        unsigned old = atomicAdd(cnt, 1u);
        s_tgt = old - old % CTAS_PER_B + CTAS_PER_B;
        while (*(volatile unsigned*)cnt < s_tgt) __nanosleep(64);
    }
    __syncthreads();
    __threadfence();                      // acquire: others' writes visible
}

// ---------------------------------------------------------------------------
// Fused persistent kernel: pass1 -> barrier -> pass2 -> barrier -> final.
// Pass bodies are the R8 structure (register double-buffered chunks).
// ---------------------------------------------------------------------------
__global__ void __launch_bounds__(TPB) fused_kernel(
    const float* __restrict__ inp, const float* __restrict__ od_all,
    const float* __restrict__ kern, const float* __restrict__ bias,
    float* __restrict__ out)
{
    __shared__ __align__(16) float s_part[CROWS * TPB];  // 16KB partials; reused as kern cache
    __shared__ float4 s_w[CROWS * 2];                    // pass1: [8]; pass2: [8][2]
    __shared__ float4 s_st[MAXCH * CROWS * 2];           // row state (pass2-sized)

    const int b    = blockIdx.x / CTAS_PER_B;
    const int slot = blockIdx.x % CTAS_PER_B;
    const int tid  = threadIdx.x;
    const int warp = tid >> 5, lane = tid & 31;
    const int nch  = (NCHUNKS - 1 - slot) / CTAS_PER_B + 1;   // 14 or 15

    // ======================= PASS 1 (K=4) =======================
    {
        const float4* ODb = reinterpret_cast<const float4*>(od_all + (size_t)(b * 2) * N * N);

        for (int L = tid; L < nch * CROWS; L += TPB) {
            int i = (slot + (L >> 3) * CTAS_PER_B) * CROWS + (L & 7);
            s_st[L] = reinterpret_cast<const float4*>(inp)[b * N + i];
        }
        __syncthreads();

        float4 dA[CROWS], dB[CROWS];
        {
            const float4* p = ODb + (size_t)slot * CROWS * (N / 4) + tid;
#pragma unroll
            for (int r = 0; r < CROWS; r++) dA[r] = p[r * (N / 4)];
        }

        float acc[4][4] = {};

        auto body = [&](float4 (&cur)[CROWS], float4 (&nxt)[CROWS], int c) {
            if (c + 1 < nch) {
                const float4* p = ODb + (size_t)(slot + (c + 1) * CTAS_PER_B) * CROWS * (N / 4) + tid;
#pragma unroll
                for (int r = 0; r < CROWS; r++) nxt[r] = p[r * (N / 4)];
            }
#pragma unroll
            for (int r = 0; r < CROWS; r++)
                s_part[r * TPB + tid] = (cur[r].x + cur[r].y) + (cur[r].z + cur[r].w);
            __syncthreads();

            if (warp < CROWS) {
                const float4* pp = reinterpret_cast<const float4*>(s_part + warp * TPB);
                float s = 0.0f;
#pragma unroll
                for (int k = 0; k < TPB / 128; k++) {
                    float4 v = pp[lane + k * 32];
                    s += (v.x + v.y) + (v.z + v.w);
                }
#pragma unroll
                for (int o = 16; o; o >>= 1) s += __shfl_xor_sync(0xffffffffu, s, o);
                if (lane == 0) {
                    float4 f = s_st[c * CROWS + warp];
                    int gi = b * N + (slot + c * CTAS_PER_B) * CROWS + warp;
                    float ratio = f.x / (DELTA + s);
                    float sc = ratio < 1.0f ? ratio : 1.0f;
                    g_odout1[gi] = sc * s;
                    float inv = 1.0f / (DELTA + f.x);
                    s_w[warp] = make_float4(sc, sc * (f.y * inv),
                                            sc * (f.z * inv), sc * (f.w * inv));
                }
            }
            __syncthreads();

#pragma unroll
            for (int r = 0; r < CROWS; r++) {
                float4 v = cur[r];
                float4 w = s_w[r];
                float wk[4] = {w.x, w.y, w.z, w.w};
#pragma unroll
                for (int k = 0; k < 4; k++) {
                    acc[0][k] = fmaf(v.x, wk[k], acc[0][k]);
                    acc[1][k] = fmaf(v.y, wk[k], acc[1][k]);
                    acc[2][k] = fmaf(v.z, wk[k], acc[2][k]);
                    acc[3][k] = fmaf(v.w, wk[k], acc[3][k]);
                }
            }
        };

        for (int c = 0; c < nch; c += 2) {
            body(dA, dB, c);
            if (c + 1 < nch) body(dB, dA, c + 1);
        }

#pragma unroll
        for (int cc = 0; cc < 4; cc++) {
            float* dst = g_colA + ((size_t)b * N + tid * 4 + cc) * 4;
#pragma unroll
            for (int k = 0; k < 4; k++) atomicAdd(dst + k, acc[cc][k]);
        }
    }

    batch_barrier(&g_cnt1[b], tid);   // pass1(batch b) fully visible

    // ======================= PASS 2 (K=7) =======================
    {
        const float4* ODb = reinterpret_cast<const float4*>(od_all + (size_t)(b * 2 + 1) * N * N);

        for (int L = tid; L < nch * CROWS; L += TPB) {
            int i  = (slot + (L >> 3) * CTAS_PER_B) * CROWS + (L & 7);
            int gi = b * N + i;
            float4 f   = reinterpret_cast<const float4*>(inp)[gi];
            float4 csA = reinterpret_cast<float4*>(g_colA)[gi];
            reinterpret_cast<float4*>(g_colA)[gi] = make_float4(0, 0, 0, 0);  // re-zero for replay
            float od1 = g_odout1[gi];
            float inv0 = 1.0f / (DELTA + f.x);
            float s60 = f.y - od1 * (f.y * inv0);
            float s61 = f.z - od1 * (f.z * inv0);
            float s62 = f.w - od1 * (f.w * inv0);
            float pop1 = f.x - od1 + csA.x;
            s_st[L * 2 + 0] = make_float4(pop1, s60, s61, s62);
            s_st[L * 2 + 1] = make_float4(csA.y, csA.z, csA.w, 0.0f);
            g_pop1[gi] = pop1;
            g_sir6[gi * 2 + 0] = make_float4(s60, s61, s62, csA.y);
            g_sir6[gi * 2 + 1] = make_float4(csA.z, csA.w, 0.0f, 0.0f);
        }
        __syncthreads();

        float4 dA[CROWS], dB[CROWS];
        {
            const float4* p = ODb + (size_t)slot * CROWS * (N / 4) + tid;
#pragma unroll
            for (int r = 0; r < CROWS; r++) dA[r] = p[r * (N / 4)];
        }

        float acc[4][7] = {};

        auto body = [&](float4 (&cur)[CROWS], float4 (&nxt)[CROWS], int c) {
            if (c + 1 < nch) {
                const float4* p = ODb + (size_t)(slot + (c + 1) * CTAS_PER_B) * CROWS * (N / 4) + tid;
#pragma unroll
                for (int r = 0; r < CROWS; r++) nxt[r] = p[r * (N / 4)];
            }
#pragma unroll
            for (int r = 0; r < CROWS; r++)
                s_part[r * TPB + tid] = (cur[r].x + cur[r].y) + (cur[r].z + cur[r].w);
            __syncthreads();

            if (warp < CROWS) {
                const float4* pp = reinterpret_cast<const float4*>(s_part + warp * TPB);
                float s = 0.0f;
#pragma unroll
                for (int k = 0; k < TPB / 128; k++) {
                    float4 v = pp[lane + k * 32];
                    s += (v.x + v.y) + (v.z + v.w);
                }
#pragma unroll
                for (int o = 16; o; o >>= 1) s += __shfl_xor_sync(0xffffffffu, s, o);
                if (lane == 0) {
                    float4 a  = s_st[(c * CROWS + warp) * 2 + 0];   // pop1, s6[0..2]
                    float4 bb = s_st[(c * CROWS + warp) * 2 + 1];   // s6[3..5]
                    int gi = b * N + (slot + c * CTAS_PER_B) * CROWS + warp;
                    float ratio = a.x / (DELTA + s);
                    float sc = ratio < 1.0f ? ratio : 1.0f;
                    g_odout2[gi] = sc * s;
                    float inv = 1.0f / (DELTA + a.x);
                    s_w[warp * 2 + 0] = make_float4(sc, sc * (a.y * inv),
                                                    sc * (a.z * inv), sc * (a.w * inv));
                    s_w[warp * 2 + 1] = make_float4(sc * (bb.x * inv), sc * (bb.y * inv),
                                                    sc * (bb.z * inv), 0.0f);
                }
            }
            __syncthreads();

#pragma unroll
            for (int r = 0; r < CROWS; r++) {
                float4 v  = cur[r];
                float4 wa = s_w[r * 2 + 0];
                float4 wb = s_w[r * 2 + 1];
                float wk[7] = {wa.x, wa.y, wa.z, wa.w, wb.x, wb.y, wb.z};
#pragma unroll
                for (int k = 0; k < 7; k++) {
                    acc[0][k] = fmaf(v.x, wk[k], acc[0][k]);
                    acc[1][k] = fmaf(v.y, wk[k], acc[1][k]);
                    acc[2][k] = fmaf(v.z, wk[k], acc[2][k]);
                    acc[3][k] = fmaf(v.w, wk[k], acc[3][k]);
                }
            }
        };

        for (int c = 0; c < nch; c += 2) {
            body(dA, dB, c);
            if (c + 1 < nch) body(dB, dA, c + 1);
        }

#pragma unroll
        for (int cc = 0; cc < 4; cc++) {
            float* dst = g_colB + ((size_t)b * N + tid * 4 + cc) * 8;
#pragma unroll
            for (int k = 0; k < 7; k++) atomicAdd(dst + k, acc[cc][k]);
        }
    }

    batch_barrier(&g_cnt2[b], tid);   // pass2(batch b) fully visible

    // ======================= FINAL (distributed) =======================
    {
        float* s_kern = s_part;                       // reuse 16KB buffer
        for (int t = tid; t < 12 * 64; t += TPB) s_kern[t] = kern[t];
        __syncthreads();

        const int rowl = tid >> 6;    // 0..7: row within 8-row group
        const int c    = tid & 63;    // output channel

        for (int idx = rowl; ; idx += 8) {
            int L = slot + idx * CTAS_PER_B;
            if (L >= N) break;
            int gi = b * N + L;

            float pop1   = g_pop1[gi];
            float odout2 = g_odout2[gi];
            float4 a   = g_sir6[gi * 2 + 0];
            float4 b4  = g_sir6[gi * 2 + 1];
            float4 cb0 = reinterpret_cast<const float4*>(g_colB)[gi * 2 + 0];
            float4 cb1 = reinterpret_cast<const float4*>(g_colB)[gi * 2 + 1];

            float dp1 = DELTA + pop1;
            float s12[12];
            s12[0] = a.x  - odout2 * dnn(a.x,  dp1);
            s12[1] = a.y  - odout2 * dnn(a.y,  dp1);
            s12[2] = a.z  - odout2 * dnn(a.z,  dp1);
            s12[3] = a.w  - odout2 * dnn(a.w,  dp1);
            s12[4] = b4.x - odout2 * dnn(b4.x, dp1);
            s12[5] = b4.y - odout2 * dnn(b4.y, dp1);
            s12[6]  = cb0.y; s12[7]  = cb0.z; s12[8]  = cb0.w;
            s12[9]  = cb1.x; s12[10] = cb1.y; s12[11] = cb1.z;

            float acc = __ldg(&bias[c]);
#pragma unroll
            for (int f = 0; f < 12; f++)
                acc = fmaf(s12[f], s_kern[f * 64 + c], acc);
            acc = fmaxf(acc, 0.0f);

            float* orow = out + (size_t)gi * 65;
            orow[1 + c] = acc;
            if (c == 0) orow[0] = pop1 - odout2 + cb0.x;
        }
        __syncthreads();   // all colB reads of this CTA's rows done

        // re-zero this CTA's colB rows for the next replay
        for (int t = tid; ; t += TPB) {
            int idx = t >> 3, k = t & 7;
            int L = slot + idx * CTAS_PER_B;
            if (L >= N) break;
            g_colB[(size_t)(b * N + L) * 8 + k] = 0.0f;
        }
    }
}

// ---------------------------------------------------------------------------
extern "C" void kernel_launch(void* const* d_in, const int* in_sizes, int n_in,
                              void* d_out, int out_size) {
    const float* inp  = (const float*)d_in[0];  // input_feature (8,2048,4)
    const float* od   = (const float*)d_in[1];  // OD_all (8,2,2048,2048)
    const float* kern = (const float*)d_in[2];  // kernel (12,64)
    const float* bias = (const float*)d_in[3];  // bias (64)
    float* out = (float*)d_out;                 // (8,2048,65)

    fused_kernel<<<GRID, TPB>>>(inp, od, kern, bias, out);
}

// round 16
// speedup vs baseline: 1.2500x; 1.1492x over previous
#include <cuda_runtime.h>

#define B 8
#define N 2048
#define BN (B * N)
#define DELTA 1e-7f

#define TPB 512
#define CROWS 8                         // rows per chunk: 8*2048*4B = 64KB
#define NCHUNKS (N / CROWS)             // 256 chunks per batch
#define CTAS_PER_B 19
#define GRID (B * CTAS_PER_B)           // 152 CTAs = full GB300 SM count
#define MAXCH ((NCHUNKS + CTAS_PER_B - 1) / CTAS_PER_B)   // 14

// Persistent scratch (__device__ globals per allocation rules).
// float arrays accessed via float4 casts are explicitly 16B-aligned (R14 lesson).
__device__ float  g_odout1[BN];
__device__ float  g_odout2[BN];
__device__ float  g_pop1[BN];
__device__ float4 g_sir6[BN * 2];                 // SIR after iter 0
__device__ __align__(16) float g_colA[BN * 4];    // iter0 colsums (re-zeroed in pass2)
__device__ __align__(16) float g_colB[BN * 8];    // iter1 colsums (re-zeroed in final)

__device__ __forceinline__ float dnn(float n, float d) { return (d == 0.0f) ? 0.0f : n / d; }

// ---------------------------------------------------------------------------
// Pass 1 (iteration 0, K=4). Register-resident chunks, double-buffered LDG.
// ---------------------------------------------------------------------------
__global__ void __launch_bounds__(TPB, 1) pass1_kernel(
    const float* __restrict__ inp, const float* __restrict__ od_all)
{
    __shared__ __align__(16) float s_part[CROWS * TPB];  // 16KB per-thread row partials
    __shared__ float4 s_w[CROWS];            // weights for current chunk
    __shared__ float4 s_st[MAXCH * CROWS];   // prefetched input features

    const int b    = blockIdx.x / CTAS_PER_B;
    const int slot = blockIdx.x % CTAS_PER_B;
    const int tid  = threadIdx.x;
    const int warp = tid >> 5, lane = tid & 31;
    const float4* ODb = reinterpret_cast<const float4*>(od_all + (size_t)(b * 2) * N * N);
    const int nch = (NCHUNKS - 1 - slot) / CTAS_PER_B + 1;   // 13 or 14

    for (int L = tid; L < nch * CROWS; L += TPB) {
        int i = (slot + (L >> 3) * CTAS_PER_B) * CROWS + (L & 7);
        s_st[L] = reinterpret_cast<const float4*>(inp)[b * N + i];
    }
    __syncthreads();

    float4 dA[CROWS], dB[CROWS];
    {   // prologue: chunk 0 -> dA
        const float4* p = ODb + (size_t)slot * CROWS * (N / 4) + tid;
#pragma unroll
        for (int r = 0; r < CROWS; r++) dA[r] = p[r * (N / 4)];
    }

    float acc[4][4] = {};

    auto body = [&](float4 (&cur)[CROWS], float4 (&nxt)[CROWS], int c) {
        // prefetch chunk c+1 into the other register set (one chunk ahead)
        if (c + 1 < nch) {
            const float4* p = ODb + (size_t)(slot + (c + 1) * CTAS_PER_B) * CROWS * (N / 4) + tid;
#pragma unroll
            for (int r = 0; r < CROWS; r++) nxt[r] = p[r * (N / 4)];
        }
        // per-thread row partials (4 columns each)
#pragma unroll
        for (int r = 0; r < CROWS; r++)
            s_part[r * TPB + tid] = (cur[r].x + cur[r].y) + (cur[r].z + cur[r].w);
        __syncthreads();

        // warp r (<8) reduces row r and computes weights
        if (warp < CROWS) {
            const float4* pp = reinterpret_cast<const float4*>(s_part + warp * TPB);
            float s = 0.0f;
#pragma unroll
            for (int k = 0; k < TPB / 128; k++) {
                float4 v = pp[lane + k * 32];
                s += (v.x + v.y) + (v.z + v.w);
            }
#pragma unroll
            for (int o = 16; o; o >>= 1) s += __shfl_xor_sync(0xffffffffu, s, o);
            if (lane == 0) {
                float4 f = s_st[c * CROWS + warp];
                int gi = b * N + (slot + c * CTAS_PER_B) * CROWS + warp;
                float ratio = f.x / (DELTA + s);              // DELTA+s > 0 always
                float sc = ratio < 1.0f ? ratio : 1.0f;
                g_odout1[gi] = sc * s;
                float inv = 1.0f / (DELTA + f.x);             // > 0 always
                s_w[warp] = make_float4(sc, sc * (f.y * inv),
                                        sc * (f.z * inv), sc * (f.w * inv));
            }
        }
        __syncthreads();

        // K=4 weighted accumulation straight from registers
#pragma unroll
        for (int r = 0; r < CROWS; r++) {
            float4 v = cur[r];
            float4 w = s_w[r];
            float wk[4] = {w.x, w.y, w.z, w.w};
#pragma unroll
            for (int k = 0; k < 4; k++) {
                acc[0][k] = fmaf(v.x, wk[k], acc[0][k]);
                acc[1][k] = fmaf(v.y, wk[k], acc[1][k]);
                acc[2][k] = fmaf(v.z, wk[k], acc[2][k]);
                acc[3][k] = fmaf(v.w, wk[k], acc[3][k]);
            }
        }
        // s_part/s_w(c+1) rewrites are fenced by the next iteration's barriers.
    };

    for (int c = 0; c < nch; c += 2) {
        body(dA, dB, c);
        if (c + 1 < nch) body(dB, dA, c + 1);
    }

#pragma unroll
    for (int cc = 0; cc < 4; cc++) {
        float* dst = g_colA + ((size_t)b * N + tid * 4 + cc) * 4;
#pragma unroll
        for (int k = 0; k < 4; k++) atomicAdd(dst + k, acc[cc][k]);
    }
}

// ---------------------------------------------------------------------------
// Pass 2 (iteration 1, K=7). Fuses update<3> in the state prefetch.
// ---------------------------------------------------------------------------
__global__ void __launch_bounds__(TPB, 1) pass2_kernel(
    const float* __restrict__ inp, const float* __restrict__ od_all)
{
    __shared__ __align__(16) float s_part[CROWS * TPB];   // 16KB
    __shared__ float4 s_w[CROWS * 2];        // 7 weights per row (2 float4)
    __shared__ float4 s_st[MAXCH * CROWS * 2];

    const int b    = blockIdx.x / CTAS_PER_B;
    const int slot = blockIdx.x % CTAS_PER_B;
    const int tid  = threadIdx.x;
    const int warp = tid >> 5, lane = tid & 31;
    const float4* ODb = reinterpret_cast<const float4*>(od_all + (size_t)(b * 2 + 1) * N * N);
    const int nch = (NCHUNKS - 1 - slot) / CTAS_PER_B + 1;

    // One-time prefetch + fused iter-0 state update; re-zero colA for replay
    for (int L = tid; L < nch * CROWS; L += TPB) {
        int i  = (slot + (L >> 3) * CTAS_PER_B) * CROWS + (L & 7);
        int gi = b * N + i;
        float4 f   = reinterpret_cast<const float4*>(inp)[gi];
        float4 csA = reinterpret_cast<float4*>(g_colA)[gi];
        reinterpret_cast<float4*>(g_colA)[gi] = make_float4(0, 0, 0, 0);
        float od1 = g_odout1[gi];
        float inv0 = 1.0f / (DELTA + f.x);
        float s60 = f.y - od1 * (f.y * inv0);
        float s61 = f.z - od1 * (f.z * inv0);
        float s62 = f.w - od1 * (f.w * inv0);
        float pop1 = f.x - od1 + csA.x;
        s_st[L * 2 + 0] = make_float4(pop1, s60, s61, s62);
        s_st[L * 2 + 1] = make_float4(csA.y, csA.z, csA.w, 0.0f);
        g_pop1[gi] = pop1;
        g_sir6[gi * 2 + 0] = make_float4(s60, s61, s62, csA.y);
        g_sir6[gi * 2 + 1] = make_float4(csA.z, csA.w, 0.0f, 0.0f);
    }
    __syncthreads();

    float4 dA[CROWS], dB[CROWS];
    {
        const float4* p = ODb + (size_t)slot * CROWS * (N / 4) + tid;
#pragma unroll
        for (int r = 0; r < CROWS; r++) dA[r] = p[r * (N / 4)];
    }

    float acc[4][7] = {};

    auto body = [&](float4 (&cur)[CROWS], float4 (&nxt)[CROWS], int c) {
        if (c + 1 < nch) {
            const float4* p = ODb + (size_t)(slot + (c + 1) * CTAS_PER_B) * CROWS * (N / 4) + tid;
#pragma unroll
            for (int r = 0; r < CROWS; r++) nxt[r] = p[r * (N / 4)];
        }
#pragma unroll
        for (int r = 0; r < CROWS; r++)
            s_part[r * TPB + tid] = (cur[r].x + cur[r].y) + (cur[r].z + cur[r].w);
        __syncthreads();

        if (warp < CROWS) {
            const float4* pp = reinterpret_cast<const float4*>(s_part + warp * TPB);
            float s = 0.0f;
#pragma unroll
            for (int k = 0; k < TPB / 128; k++) {
                float4 v = pp[lane + k * 32];
                s += (v.x + v.y) + (v.z + v.w);
            }
#pragma unroll
            for (int o = 16; o; o >>= 1) s += __shfl_xor_sync(0xffffffffu, s, o);
            if (lane == 0) {
                float4 a  = s_st[(c * CROWS + warp) * 2 + 0];   // pop1, s6[0..2]
                float4 bb = s_st[(c * CROWS + warp) * 2 + 1];   // s6[3..5]
                int gi = b * N + (slot + c * CTAS_PER_B) * CROWS + warp;
                float ratio = a.x / (DELTA + s);
                float sc = ratio < 1.0f ? ratio : 1.0f;
                g_odout2[gi] = sc * s;
                float inv = 1.0f / (DELTA + a.x);
                s_w[warp * 2 + 0] = make_float4(sc, sc * (a.y * inv),
                                                sc * (a.z * inv), sc * (a.w * inv));
                s_w[warp * 2 + 1] = make_float4(sc * (bb.x * inv), sc * (bb.y * inv),
                                                sc * (bb.z * inv), 0.0f);
            }
        }
        __syncthreads();

#pragma unroll
        for (int r = 0; r < CROWS; r++) {
            float4 v  = cur[r];
            float4 wa = s_w[r * 2 + 0];
            float4 wb = s_w[r * 2 + 1];
            float wk[7] = {wa.x, wa.y, wa.z, wa.w, wb.x, wb.y, wb.z};
#pragma unroll
            for (int k = 0; k < 7; k++) {
                acc[0][k] = fmaf(v.x, wk[k], acc[0][k]);
                acc[1][k] = fmaf(v.y, wk[k], acc[1][k]);
                acc[2][k] = fmaf(v.z, wk[k], acc[2][k]);
                acc[3][k] = fmaf(v.w, wk[k], acc[3][k]);
            }
        }
    };

    for (int c = 0; c < nch; c += 2) {
        body(dA, dB, c);
        if (c + 1 < nch) body(dB, dA, c + 1);
    }

#pragma unroll
    for (int cc = 0; cc < 4; cc++) {
        float* dst = g_colB + ((size_t)b * N + tid * 4 + cc) * 8;
#pragma unroll
        for (int k = 0; k < 7; k++) atomicAdd(dst + k, acc[cc][k]);
    }
}

// ---------------------------------------------------------------------------
// Final: fuses update<6> + GEMM(12->64) + relu + concat(pop). Re-zeros colB.
// ---------------------------------------------------------------------------
__global__ void __launch_bounds__(256) final_kernel(
    const float* __restrict__ kern,
    const float* __restrict__ bias,
    float* __restrict__ out)
{
    __shared__ float s_kern[12 * 64];
    const int tid = threadIdx.x;
    for (int t = tid; t < 12 * 64; t += 256) s_kern[t] = kern[t];
    __syncthreads();

    const int rowl = tid >> 6;
    const int c    = tid & 63;
    const int gi   = blockIdx.x * 4 + rowl;

    float pop1   = g_pop1[gi];
    float odout2 = g_odout2[gi];
    float4 a   = g_sir6[gi * 2 + 0];
    float4 b4  = g_sir6[gi * 2 + 1];
    float4 cb0 = reinterpret_cast<const float4*>(g_colB)[gi * 2 + 0];
    float4 cb1 = reinterpret_cast<const float4*>(g_colB)[gi * 2 + 1];

    float dp1 = DELTA + pop1;
    float s12[12];
    s12[0] = a.x  - odout2 * dnn(a.x,  dp1);
    s12[1] = a.y  - odout2 * dnn(a.y,  dp1);
    s12[2] = a.z  - odout2 * dnn(a.z,  dp1);
    s12[3] = a.w  - odout2 * dnn(a.w,  dp1);
    s12[4] = b4.x - odout2 * dnn(b4.x, dp1);
    s12[5] = b4.y - odout2 * dnn(b4.y, dp1);
    s12[6]  = cb0.y; s12[7]  = cb0.z; s12[8]  = cb0.w;
    s12[9]  = cb1.x; s12[10] = cb1.y; s12[11] = cb1.z;

    float acc = __ldg(&bias[c]);
#pragma unroll
    for (int f = 0; f < 12; f++)
        acc = fmaf(s12[f], s_kern[f * 64 + c], acc);
    acc = fmaxf(acc, 0.0f);

    float* orow = out + (size_t)gi * 65;
    orow[1 + c] = acc;
    if (c == 0) orow[0] = pop1 - odout2 + cb0.x;

    __syncthreads();                  // all colB reads done before re-zero
    if (c < 8) g_colB[gi * 8 + c] = 0.0f;
}

// ---------------------------------------------------------------------------
extern "C" void kernel_launch(void* const* d_in, const int* in_sizes, int n_in,
                              void* d_out, int out_size) {
    const float* inp  = (const float*)d_in[0];  // input_feature (8,2048,4)
    const float* od   = (const float*)d_in[1];  // OD_all (8,2,2048,2048)
    const float* kern = (const float*)d_in[2];  // kernel (12,64)
    const float* bias = (const float*)d_in[3];  // bias (64)
    float* out = (float*)d_out;                 // (8,2048,65)

    pass1_kernel<<<GRID, TPB>>>(inp, od);
    pass2_kernel<<<GRID, TPB>>>(inp, od);
    final_kernel<<<BN / 4, 256>>>(kern, bias, out);
}

// round 17
// speedup vs baseline: 1.2540x; 1.0032x over previous
#include <cuda_runtime.h>

#define B 8
#define N 2048
#define BN (B * N)
#define DELTA 1e-7f

#define TPB 512
#define CROWS 8                         // rows per chunk: 8*2048*4B = 64KB
#define NCHUNKS (N / CROWS)             // 256 chunks per batch
#define CTAS_PER_B 18
#define GRID (B * CTAS_PER_B)           // 144 CTAs (1 per SM) — measured optimum
#define MAXCH ((NCHUNKS + CTAS_PER_B - 1) / CTAS_PER_B)   // 15

// Persistent scratch (__device__ globals per allocation rules).
// float arrays accessed via float4 casts are explicitly 16B-aligned (R14 lesson).
__device__ float  g_odout1[BN];
__device__ float  g_odout2[BN];
__device__ float  g_pop1[BN];
__device__ float4 g_sir6[BN * 2];                 // SIR after iter 0
__device__ __align__(16) float g_colA[BN * 4];    // iter0 colsums (re-zeroed in pass2)
__device__ __align__(16) float g_colB[BN * 8];    // iter1 colsums (re-zeroed in final)

__device__ __forceinline__ float dnn(float n, float d) { return (d == 0.0f) ? 0.0f : n / d; }

// ---------------------------------------------------------------------------
// Pass 1 (iteration 0, K=4). Register-resident chunks, double-buffered LDG.
// ---------------------------------------------------------------------------
__global__ void __launch_bounds__(TPB, 1) pass1_kernel(
    const float* __restrict__ inp, const float* __restrict__ od_all)
{
    __shared__ __align__(16) float s_part[CROWS * TPB];  // 16KB per-thread row partials
    __shared__ float4 s_w[CROWS];            // weights for current chunk
    __shared__ float4 s_st[MAXCH * CROWS];   // prefetched input features

    const int b    = blockIdx.x / CTAS_PER_B;
    const int slot = blockIdx.x % CTAS_PER_B;
    const int tid  = threadIdx.x;
    const int warp = tid >> 5, lane = tid & 31;
    const float4* ODb = reinterpret_cast<const float4*>(od_all + (size_t)(b * 2) * N * N);
    const int nch = (NCHUNKS - 1 - slot) / CTAS_PER_B + 1;   // 14 or 15

    for (int L = tid; L < nch * CROWS; L += TPB) {
        int i = (slot + (L >> 3) * CTAS_PER_B) * CROWS + (L & 7);
        s_st[L] = reinterpret_cast<const float4*>(inp)[b * N + i];
    }
    __syncthreads();

    float4 dA[CROWS], dB[CROWS];
    {   // prologue: chunk 0 -> dA
        const float4* p = ODb + (size_t)slot * CROWS * (N / 4) + tid;
#pragma unroll
        for (int r = 0; r < CROWS; r++) dA[r] = p[r * (N / 4)];
    }

    float acc[4][4] = {};

    auto body = [&](float4 (&cur)[CROWS], float4 (&nxt)[CROWS], int c) {
        // prefetch chunk c+1 into the other register set (one chunk ahead)
        if (c + 1 < nch) {
            const float4* p = ODb + (size_t)(slot + (c + 1) * CTAS_PER_B) * CROWS * (N / 4) + tid;
#pragma unroll
            for (int r = 0; r < CROWS; r++) nxt[r] = p[r * (N / 4)];
        }
        // per-thread row partials (4 columns each)
#pragma unroll
        for (int r = 0; r < CROWS; r++)
            s_part[r * TPB + tid] = (cur[r].x + cur[r].y) + (cur[r].z + cur[r].w);
        __syncthreads();

        // warp r (<8) reduces row r and computes weights
        if (warp < CROWS) {
            const float4* pp = reinterpret_cast<const float4*>(s_part + warp * TPB);
            float s = 0.0f;
#pragma unroll
            for (int k = 0; k < TPB / 128; k++) {
                float4 v = pp[lane + k * 32];
                s += (v.x + v.y) + (v.z + v.w);
            }
#pragma unroll
            for (int o = 16; o; o >>= 1) s += __shfl_xor_sync(0xffffffffu, s, o);
            if (lane == 0) {
                float4 f = s_st[c * CROWS + warp];
                int gi = b * N + (slot + c * CTAS_PER_B) * CROWS + warp;
                float ratio = f.x / (DELTA + s);              // DELTA+s > 0 always
                float sc = ratio < 1.0f ? ratio : 1.0f;
                g_odout1[gi] = sc * s;
                float inv = 1.0f / (DELTA + f.x);             // > 0 always
                s_w[warp] = make_float4(sc, sc * (f.y * inv),
                                        sc * (f.z * inv), sc * (f.w * inv));
            }
        }
        __syncthreads();

        // K=4 weighted accumulation straight from registers
#pragma unroll
        for (int r = 0; r < CROWS; r++) {
            float4 v = cur[r];
            float4 w = s_w[r];
            float wk[4] = {w.x, w.y, w.z, w.w};
#pragma unroll
            for (int k = 0; k < 4; k++) {
                acc[0][k] = fmaf(v.x, wk[k], acc[0][k]);
                acc[1][k] = fmaf(v.y, wk[k], acc[1][k]);
                acc[2][k] = fmaf(v.z, wk[k], acc[2][k]);
                acc[3][k] = fmaf(v.w, wk[k], acc[3][k]);
            }
        }
        // s_part/s_w(c+1) rewrites are fenced by the next iteration's barriers.
    };

    for (int c = 0; c < nch; c += 2) {
        body(dA, dB, c);
        if (c + 1 < nch) body(dB, dA, c + 1);
    }

#pragma unroll
    for (int cc = 0; cc < 4; cc++) {
        float* dst = g_colA + ((size_t)b * N + tid * 4 + cc) * 4;
#pragma unroll
        for (int k = 0; k < 4; k++) atomicAdd(dst + k, acc[cc][k]);
    }
}

// ---------------------------------------------------------------------------
// Pass 2 (iteration 1, K=7). Fuses update<3> in the state prefetch.
// ---------------------------------------------------------------------------
__global__ void __launch_bounds__(TPB, 1) pass2_kernel(
    const float* __restrict__ inp, const float* __restrict__ od_all)
{
    __shared__ __align__(16) float s_part[CROWS * TPB];   // 16KB
    __shared__ float4 s_w[CROWS * 2];        // 7 weights per row (2 float4)
    __shared__ float4 s_st[MAXCH * CROWS * 2];

    const int b    = blockIdx.x / CTAS_PER_B;
    const int slot = blockIdx.x % CTAS_PER_B;
    const int tid  = threadIdx.x;
    const int warp = tid >> 5, lane = tid & 31;
    const float4* ODb = reinterpret_cast<const float4*>(od_all + (size_t)(b * 2 + 1) * N * N);
    const int nch = (NCHUNKS - 1 - slot) / CTAS_PER_B + 1;

    // One-time prefetch + fused iter-0 state update; re-zero colA for replay
    for (int L = tid; L < nch * CROWS; L += TPB) {
        int i  = (slot + (L >> 3) * CTAS_PER_B) * CROWS + (L & 7);
        int gi = b * N + i;
        float4 f   = reinterpret_cast<const float4*>(inp)[gi];
        float4 csA = reinterpret_cast<float4*>(g_colA)[gi];
        reinterpret_cast<float4*>(g_colA)[gi] = make_float4(0, 0, 0, 0);
        float od1 = g_odout1[gi];
        float inv0 = 1.0f / (DELTA + f.x);
        float s60 = f.y - od1 * (f.y * inv0);
        float s61 = f.z - od1 * (f.z * inv0);
        float s62 = f.w - od1 * (f.w * inv0);
        float pop1 = f.x - od1 + csA.x;
        s_st[L * 2 + 0] = make_float4(pop1, s60, s61, s62);
        s_st[L * 2 + 1] = make_float4(csA.y, csA.z, csA.w, 0.0f);
        g_pop1[gi] = pop1;
        g_sir6[gi * 2 + 0] = make_float4(s60, s61, s62, csA.y);
        g_sir6[gi * 2 + 1] = make_float4(csA.z, csA.w, 0.0f, 0.0f);
    }
    __syncthreads();

    float4 dA[CROWS], dB[CROWS];
    {
        const float4* p = ODb + (size_t)slot * CROWS * (N / 4) + tid;
#pragma unroll
        for (int r = 0; r < CROWS; r++) dA[r] = p[r * (N / 4)];
    }

    float acc[4][7] = {};

    auto body = [&](float4 (&cur)[CROWS], float4 (&nxt)[CROWS], int c) {
        if (c + 1 < nch) {
            const float4* p = ODb + (size_t)(slot + (c + 1) * CTAS_PER_B) * CROWS * (N / 4) + tid;
#pragma unroll
            for (int r = 0; r < CROWS; r++) nxt[r] = p[r * (N / 4)];
        }
#pragma unroll
        for (int r = 0; r < CROWS; r++)
            s_part[r * TPB + tid] = (cur[r].x + cur[r].y) + (cur[r].z + cur[r].w);
        __syncthreads();

        if (warp < CROWS) {
            const float4* pp = reinterpret_cast<const float4*>(s_part + warp * TPB);
            float s = 0.0f;
#pragma unroll
            for (int k = 0; k < TPB / 128; k++) {
                float4 v = pp[lane + k * 32];
                s += (v.x + v.y) + (v.z + v.w);
            }
#pragma unroll
            for (int o = 16; o; o >>= 1) s += __shfl_xor_sync(0xffffffffu, s, o);
            if (lane == 0) {
                float4 a  = s_st[(c * CROWS + warp) * 2 + 0];   // pop1, s6[0..2]
                float4 bb = s_st[(c * CROWS + warp) * 2 + 1];   // s6[3..5]
                int gi = b * N + (slot + c * CTAS_PER_B) * CROWS + warp;
                float ratio = a.x / (DELTA + s);
                float sc = ratio < 1.0f ? ratio : 1.0f;
                g_odout2[gi] = sc * s;
                float inv = 1.0f / (DELTA + a.x);
                s_w[warp * 2 + 0] = make_float4(sc, sc * (a.y * inv),
                                                sc * (a.z * inv), sc * (a.w * inv));
                s_w[warp * 2 + 1] = make_float4(sc * (bb.x * inv), sc * (bb.y * inv),
                                                sc * (bb.z * inv), 0.0f);
            }
        }
        __syncthreads();

#pragma unroll
        for (int r = 0; r < CROWS; r++) {
            float4 v  = cur[r];
            float4 wa = s_w[r * 2 + 0];
            float4 wb = s_w[r * 2 + 1];
            float wk[7] = {wa.x, wa.y, wa.z, wa.w, wb.x, wb.y, wb.z};
#pragma unroll
            for (int k = 0; k < 7; k++) {
                acc[0][k] = fmaf(v.x, wk[k], acc[0][k]);
                acc[1][k] = fmaf(v.y, wk[k], acc[1][k]);
                acc[2][k] = fmaf(v.z, wk[k], acc[2][k]);
                acc[3][k] = fmaf(v.w, wk[k], acc[3][k]);
            }
        }
    };

    for (int c = 0; c < nch; c += 2) {
        body(dA, dB, c);
        if (c + 1 < nch) body(dB, dA, c + 1);
    }

#pragma unroll
    for (int cc = 0; cc < 4; cc++) {
        float* dst = g_colB + ((size_t)b * N + tid * 4 + cc) * 8;
#pragma unroll
        for (int k = 0; k < 7; k++) atomicAdd(dst + k, acc[cc][k]);
    }
}

// ---------------------------------------------------------------------------
// Final: fuses update<6> + GEMM(12->64) + relu + concat(pop). Re-zeros colB.
// ---------------------------------------------------------------------------
__global__ void __launch_bounds__(256) final_kernel(
    const float* __restrict__ kern,
    const float* __restrict__ bias,
    float* __restrict__ out)
{
    __shared__ float s_kern[12 * 64];
    const int tid = threadIdx.x;
    for (int t = tid; t < 12 * 64; t += 256) s_kern[t] = kern[t];
    __syncthreads();

    const int rowl = tid >> 6;
    const int c    = tid & 63;
    const int gi   = blockIdx.x * 4 + rowl;

    float pop1   = g_pop1[gi];
    float odout2 = g_odout2[gi];
    float4 a   = g_sir6[gi * 2 + 0];
    float4 b4  = g_sir6[gi * 2 + 1];
    float4 cb0 = reinterpret_cast<const float4*>(g_colB)[gi * 2 + 0];
    float4 cb1 = reinterpret_cast<const float4*>(g_colB)[gi * 2 + 1];

    float dp1 = DELTA + pop1;
    float s12[12];
    s12[0] = a.x  - odout2 * dnn(a.x,  dp1);
    s12[1] = a.y  - odout2 * dnn(a.y,  dp1);
    s12[2] = a.z  - odout2 * dnn(a.z,  dp1);
    s12[3] = a.w  - odout2 * dnn(a.w,  dp1);
    s12[4] = b4.x - odout2 * dnn(b4.x, dp1);
    s12[5] = b4.y - odout2 * dnn(b4.y, dp1);
    s12[6]  = cb0.y; s12[7]  = cb0.z; s12[8]  = cb0.w;
    s12[9]  = cb1.x; s12[10] = cb1.y; s12[11] = cb1.z;

    float acc = __ldg(&bias[c]);
#pragma unroll
    for (int f = 0; f < 12; f++)
        acc = fmaf(s12[f], s_kern[f * 64 + c], acc);
    acc = fmaxf(acc, 0.0f);

    float* orow = out + (size_t)gi * 65;
    orow[1 + c] = acc;
    if (c == 0) orow[0] = pop1 - odout2 + cb0.x;

    __syncthreads();                  // all colB reads done before re-zero
    if (c < 8) g_colB[gi * 8 + c] = 0.0f;
}

// ---------------------------------------------------------------------------
extern "C" void kernel_launch(void* const* d_in, const int* in_sizes, int n_in,
                              void* d_out, int out_size) {
    const float* inp  = (const float*)d_in[0];  // input_feature (8,2048,4)
    const float* od   = (const float*)d_in[1];  // OD_all (8,2,2048,2048)
    const float* kern = (const float*)d_in[2];  // kernel (12,64)
    const float* bias = (const float*)d_in[3];  // bias (64)
    float* out = (float*)d_out;                 // (8,2048,65)

    pass1_kernel<<<GRID, TPB>>>(inp, od);
    pass2_kernel<<<GRID, TPB>>>(inp, od);
    final_kernel<<<BN / 4, 256>>>(kern, bias, out);
}